// round 2
// baseline (speedup 1.0000x reference)
#include <cuda_runtime.h>
#include <math.h>

#define S_ 512
#define B_ 8
#define D_ 512
#define H_ 8
#define HD_ 64
#define E_ 4
#define L_ 6
#define FF_ 2048
#define V_ 32000
#define N_ 4096          // S_*B_
#define EPS_ 1e-5f
#define NEGINF_ (-3.402823466e38f)

// ---------------- scratch (static device globals; no allocation) ----------------
__device__ float g_x[N_*D_];          // activations [N, D], n = s*B + b
__device__ float g_tmp[N_*D_];        // residual branch
__device__ float g_q[E_*N_*D_];       // Q per expert (later reused as expert-output eo)
__device__ float g_k[E_*N_*D_];
__device__ float g_v[E_*N_*D_];
__device__ float g_ctx[E_*N_*D_];
__device__ float g_h[N_*FF_];         // FFN hidden
__device__ float g_gate[N_*E_];       // softmaxed gate
__device__ float g_aux;               // aux loss accumulator

// ---------------- embed + positional encoding (+ zero aux) ----------------
__global__ void embed_kernel(const int* __restrict__ src, const float* __restrict__ emb) {
    int n = blockIdx.x;
    int s = n / B_;
    if (n == 0 && threadIdx.x == 0) g_aux = 0.f;
    int tok = src[n];
    const float scale = 22.62741699796952f;  // sqrt(512)
    for (int d = threadIdx.x; d < D_; d += blockDim.x) {
        int j = d >> 1;
        float div = expf((float)(2*j) * (-9.210340371976184f / (float)D_));
        float ang = (float)s * div;
        float pe = (d & 1) ? cosf(ang) : sinf(ang);
        g_x[(size_t)n*D_ + d] = emb[(size_t)tok*D_ + d] * scale + pe;
    }
}

// ---------------- gate: softmax(x @ gate_w + gate_b) over E=4 ----------------
__global__ void gate_kernel(const float* __restrict__ gw, const float* __restrict__ gb) {
    int n = blockIdx.x;
    int t = threadIdx.x;           // 128 threads
    float p0=0.f, p1=0.f, p2=0.f, p3=0.f;
    for (int d = t; d < D_; d += 128) {
        float xv = g_x[(size_t)n*D_ + d];
        const float* w = gw + (size_t)d*E_;
        p0 = fmaf(xv, w[0], p0);
        p1 = fmaf(xv, w[1], p1);
        p2 = fmaf(xv, w[2], p2);
        p3 = fmaf(xv, w[3], p3);
    }
    __shared__ float red[4][128];
    red[0][t]=p0; red[1][t]=p1; red[2][t]=p2; red[3][t]=p3;
    __syncthreads();
    for (int off = 64; off > 0; off >>= 1) {
        if (t < off) {
            red[0][t]+=red[0][t+off]; red[1][t]+=red[1][t+off];
            red[2][t]+=red[2][t+off]; red[3][t]+=red[3][t+off];
        }
        __syncthreads();
    }
    if (t == 0) {
        float l0=red[0][0]+gb[0], l1=red[1][0]+gb[1], l2=red[2][0]+gb[2], l3=red[3][0]+gb[3];
        float mx = fmaxf(fmaxf(l0,l1), fmaxf(l2,l3));
        float e0=expf(l0-mx), e1=expf(l1-mx), e2=expf(l2-mx), e3=expf(l3-mx);
        float inv = 1.f / (e0+e1+e2+e3);
        g_gate[n*4+0]=e0*inv; g_gate[n*4+1]=e1*inv; g_gate[n*4+2]=e2*inv; g_gate[n*4+3]=e3*inv;
    }
}

// ---------------- aux loss: importance over tokens, CV^2 accumulate ----------------
__global__ void aux_kernel() {
    __shared__ float red[4][256];
    int t = threadIdx.x;           // 256 threads
    float p[4] = {0.f,0.f,0.f,0.f};
    for (int n = t; n < N_; n += 256) {
        p[0]+=g_gate[n*4+0]; p[1]+=g_gate[n*4+1];
        p[2]+=g_gate[n*4+2]; p[3]+=g_gate[n*4+3];
    }
    red[0][t]=p[0]; red[1][t]=p[1]; red[2][t]=p[2]; red[3][t]=p[3];
    __syncthreads();
    for (int off = 128; off > 0; off >>= 1) {
        if (t < off) {
            red[0][t]+=red[0][t+off]; red[1][t]+=red[1][t+off];
            red[2][t]+=red[2][t+off]; red[3][t]+=red[3][t+off];
        }
        __syncthreads();
    }
    if (t == 0) {
        float i0=red[0][0], i1=red[1][0], i2=red[2][0], i3=red[3][0];
        float mean = (i0+i1+i2+i3)*0.25f;
        float d0=i0-mean, d1=i1-mean, d2=i2-mean, d3=i3-mean;
        float var = (d0*d0+d1*d1+d2*d2+d3*d3)*0.25f;
        g_aux += var / (mean*mean + 1e-10f);
    }
}

// ---------------- generic tiled GEMM: C = A(NxK) @ W(KxM) + bias, optional relu ----
// 64x64 tile, 256 threads, 4x4 microtile; blockIdx.z selects a batched slice via strides.
__global__ __launch_bounds__(256) void gemm_kernel(
    const float* __restrict__ A, const float* __restrict__ W,
    const float* __restrict__ bias, float* __restrict__ C,
    int N, int K, int M,
    size_t az, size_t wz, size_t bz, size_t cz, int relu)
{
    A    += (size_t)blockIdx.z * az;
    W    += (size_t)blockIdx.z * wz;
    bias += (size_t)blockIdx.z * bz;
    C    += (size_t)blockIdx.z * cz;

    __shared__ float As[16][68];   // transposed A tile [k][n], padded
    __shared__ float Ws[16][64];   // W tile [k][m]

    int t  = threadIdx.x;
    int tx = t & 15, ty = t >> 4;
    int n0 = blockIdx.y * 64, m0 = blockIdx.x * 64;
    int ar = t >> 2,  ac = (t & 3) * 4;     // A load: row 0..63, 4-col group
    int wk = t >> 4,  wc = (t & 15) * 4;    // W load: k 0..15, 4-col group

    float c[4][4];
    #pragma unroll
    for (int i=0;i<4;i++)
        #pragma unroll
        for (int j=0;j<4;j++) c[i][j]=0.f;

    for (int k0 = 0; k0 < K; k0 += 16) {
        float4 av = *(const float4*)(A + (size_t)(n0+ar)*K + k0 + ac);
        As[ac+0][ar]=av.x; As[ac+1][ar]=av.y; As[ac+2][ar]=av.z; As[ac+3][ar]=av.w;
        *(float4*)(&Ws[wk][wc]) = *(const float4*)(W + (size_t)(k0+wk)*M + m0 + wc);
        __syncthreads();
        #pragma unroll
        for (int kk = 0; kk < 16; kk++) {
            float4 a = *(const float4*)(&As[kk][ty*4]);
            float4 w = *(const float4*)(&Ws[kk][tx*4]);
            float aa[4] = {a.x,a.y,a.z,a.w};
            float ww[4] = {w.x,w.y,w.z,w.w};
            #pragma unroll
            for (int i=0;i<4;i++)
                #pragma unroll
                for (int j=0;j<4;j++)
                    c[i][j] = fmaf(aa[i], ww[j], c[i][j]);
        }
        __syncthreads();
    }

    int col = m0 + tx*4;
    float4 bv = *(const float4*)(bias + col);
    #pragma unroll
    for (int i=0;i<4;i++) {
        int row = n0 + ty*4 + i;
        float4 o;
        o.x = c[i][0]+bv.x; o.y = c[i][1]+bv.y; o.z = c[i][2]+bv.z; o.w = c[i][3]+bv.w;
        if (relu) { o.x=fmaxf(o.x,0.f); o.y=fmaxf(o.y,0.f); o.z=fmaxf(o.z,0.f); o.w=fmaxf(o.w,0.f); }
        *(float4*)(C + (size_t)row*M + col) = o;
    }
}

// ---------------- causal attention per (b,e,h): flash-style online softmax ---------
// grid: (4 q-chunks of 128, B*E*H=256). 128 threads; thread = one query row.
__global__ __launch_bounds__(128) void attn_kernel() {
    int qc  = blockIdx.x;
    int beh = blockIdx.y;
    int h = beh & 7;
    int e = (beh >> 3) & 3;
    int b = beh >> 5;
    int t = threadIdx.x;
    int s = qc*128 + t;

    __shared__ float4 Ks[64][16];
    __shared__ float4 Vs[64][16];

    size_t base = (size_t)e*N_*D_ + (size_t)h*HD_;
    const float* qp = g_q + base + (size_t)(s*B_+b)*D_;

    float4 q4[16];
    #pragma unroll
    for (int i=0;i<16;i++) q4[i] = *(const float4*)(qp + i*4);

    float4 a4[16];
    #pragma unroll
    for (int i=0;i<16;i++) a4[i] = make_float4(0.f,0.f,0.f,0.f);
    float m = NEGINF_, lsum = 0.f;

    int nkc = 2*qc + 2;   // key chunks of 64 needed to cover s <= qc*128+127
    for (int kc = 0; kc < nkc; kc++) {
        int j0 = kc * 64;
        __syncthreads();
        #pragma unroll
        for (int i=0;i<8;i++) {
            int idx = t + i*128;
            int j = idx >> 4, cc = idx & 15;
            size_t off = base + (size_t)((j0+j)*B_ + b)*D_ + cc*4;
            Ks[j][cc] = *(const float4*)(g_k + off);
            Vs[j][cc] = *(const float4*)(g_v + off);
        }
        __syncthreads();
        for (int j = 0; j < 64; j++) {
            int jj = j0 + j;
            if (jj > s) break;
            float s0=0.f,s1=0.f,s2=0.f,s3=0.f;
            #pragma unroll
            for (int i=0;i<16;i++) {
                float4 kk = Ks[j][i];
                s0 = fmaf(q4[i].x, kk.x, s0);
                s1 = fmaf(q4[i].y, kk.y, s1);
                s2 = fmaf(q4[i].z, kk.z, s2);
                s3 = fmaf(q4[i].w, kk.w, s3);
            }
            float sc = ((s0+s1)+(s2+s3)) * 0.125f;  // / sqrt(64)
            float mn = fmaxf(m, sc);
            float p  = __expf(sc - mn);
            if (mn > m) {
                float alpha = __expf(m - mn);
                lsum *= alpha;
                #pragma unroll
                for (int i=0;i<16;i++) {
                    a4[i].x*=alpha; a4[i].y*=alpha; a4[i].z*=alpha; a4[i].w*=alpha;
                }
                m = mn;
            }
            lsum += p;
            #pragma unroll
            for (int i=0;i<16;i++) {
                float4 vv = Vs[j][i];
                a4[i].x = fmaf(p, vv.x, a4[i].x);
                a4[i].y = fmaf(p, vv.y, a4[i].y);
                a4[i].z = fmaf(p, vv.z, a4[i].z);
                a4[i].w = fmaf(p, vv.w, a4[i].w);
            }
        }
    }
    float inv = 1.f / lsum;
    float* op = g_ctx + base + (size_t)(s*B_+b)*D_;
    #pragma unroll
    for (int i=0;i<16;i++) {
        float4 o = make_float4(a4[i].x*inv, a4[i].y*inv, a4[i].z*inv, a4[i].w*inv);
        *(float4*)(op + i*4) = o;
    }
}

// ---------------- gate-weighted expert combine: tmp = sum_e gate[n,e]*eo[e][n] ------
__global__ void combine_kernel() {
    int idx = blockIdx.x*256 + threadIdx.x;   // float4 index over N_*D_/4
    int n = idx >> 7;                         // D_/4 = 128
    const float4* eo = (const float4*)g_q;    // eo lives in g_q
    const int z = N_*D_/4;
    float g0=g_gate[n*4+0], g1=g_gate[n*4+1], g2=g_gate[n*4+2], g3=g_gate[n*4+3];
    float4 v0=eo[idx], v1=eo[z+idx], v2=eo[2*z+idx], v3=eo[3*z+idx];
    float4 r;
    r.x = g0*v0.x + g1*v1.x + g2*v2.x + g3*v3.x;
    r.y = g0*v0.y + g1*v1.y + g2*v2.y + g3*v3.y;
    r.z = g0*v0.z + g1*v1.z + g2*v2.z + g3*v3.z;
    r.w = g0*v0.w + g1*v1.w + g2*v2.w + g3*v3.w;
    ((float4*)g_tmp)[idx] = r;
}

// ---------------- LayerNorm (optional residual add), 1 block per token ----------
__device__ __forceinline__ float blocksum128(float v) {
    __shared__ float sh[4];
    #pragma unroll
    for (int o=16;o>0;o>>=1) v += __shfl_down_sync(0xffffffffu, v, o);
    __syncthreads();
    if ((threadIdx.x & 31) == 0) sh[threadIdx.x >> 5] = v;
    __syncthreads();
    return sh[0]+sh[1]+sh[2]+sh[3];
}

__global__ void ln_kernel(const float* __restrict__ xin, const float* __restrict__ res,
                          const float* __restrict__ g, const float* __restrict__ bb,
                          float* __restrict__ out) {
    int n = blockIdx.x, t = threadIdx.x;   // 128 threads, D/4 float4s
    float4 v = ((const float4*)(xin + (size_t)n*D_))[t];
    if (res) {
        float4 r = ((const float4*)(res + (size_t)n*D_))[t];
        v.x+=r.x; v.y+=r.y; v.z+=r.z; v.w+=r.w;
    }
    float mean = blocksum128(v.x+v.y+v.z+v.w) * (1.f/D_);
    float d0=v.x-mean, d1=v.y-mean, d2=v.z-mean, d3=v.w-mean;
    float var = blocksum128(d0*d0+d1*d1+d2*d2+d3*d3) * (1.f/D_);
    float rstd = rsqrtf(var + EPS_);
    float4 gg = ((const float4*)g)[t];
    float4 bv = ((const float4*)bb)[t];
    float4 o;
    o.x = d0*rstd*gg.x + bv.x;
    o.y = d1*rstd*gg.y + bv.y;
    o.z = d2*rstd*gg.z + bv.z;
    o.w = d3*rstd*gg.w + bv.w;
    ((float4*)(out + (size_t)n*D_))[t] = o;
}

// ---------------- in-place log_softmax over V per row ----------------
__global__ void lsm_kernel(float* __restrict__ out) {
    __shared__ float sh[8];
    int n = blockIdx.x, t = threadIdx.x;   // 256 threads
    float* row = out + (size_t)n*V_;
    float mx = NEGINF_;
    for (int v=t; v<V_; v+=256) mx = fmaxf(mx, row[v]);
    #pragma unroll
    for (int o=16;o>0;o>>=1) mx = fmaxf(mx, __shfl_xor_sync(0xffffffffu, mx, o));
    if ((t&31)==0) sh[t>>5]=mx;
    __syncthreads();
    mx = fmaxf(fmaxf(fmaxf(sh[0],sh[1]),fmaxf(sh[2],sh[3])),
               fmaxf(fmaxf(sh[4],sh[5]),fmaxf(sh[6],sh[7])));
    float sum = 0.f;
    for (int v=t; v<V_; v+=256) sum += expf(row[v]-mx);
    #pragma unroll
    for (int o=16;o>0;o>>=1) sum += __shfl_xor_sync(0xffffffffu, sum, o);
    __syncthreads();
    if ((t&31)==0) sh[t>>5]=sum;
    __syncthreads();
    sum = ((sh[0]+sh[1])+(sh[2]+sh[3])) + ((sh[4]+sh[5])+(sh[6]+sh[7]));
    float lse = mx + logf(sum);
    for (int v=t; v<V_; v+=256) row[v] -= lse;
}

__global__ void write_aux_kernel(float* __restrict__ out) {
    out[(size_t)N_*V_] = g_aux;
}

// ---------------- host orchestration ----------------
extern "C" void kernel_launch(void* const* d_in, const int* in_sizes, int n_in,
                              void* d_out, int out_size) {
    (void)in_sizes; (void)n_in;
    const int*   src    = (const int*)  d_in[1];
    const float* emb    = (const float*)d_in[2];
    const float* gate_w = (const float*)d_in[3];
    const float* gate_b = (const float*)d_in[4];
    const float* wq     = (const float*)d_in[5];
    const float* wk     = (const float*)d_in[6];
    const float* wv     = (const float*)d_in[7];
    const float* wo     = (const float*)d_in[8];
    const float* bq     = (const float*)d_in[9];
    const float* bk     = (const float*)d_in[10];
    const float* bv     = (const float*)d_in[11];
    const float* bo     = (const float*)d_in[12];
    const float* w1     = (const float*)d_in[13];
    const float* b1     = (const float*)d_in[14];
    const float* w2     = (const float*)d_in[15];
    const float* b2     = (const float*)d_in[16];
    const float* ln1_g  = (const float*)d_in[17];
    const float* ln1_b  = (const float*)d_in[18];
    const float* ln2_g  = (const float*)d_in[19];
    const float* ln2_b  = (const float*)d_in[20];
    const float* ln3_g  = (const float*)d_in[21];
    const float* ln3_b  = (const float*)d_in[22];
    const float* lnf_g  = (const float*)d_in[23];
    const float* lnf_b  = (const float*)d_in[24];
    const float* out_w  = (const float*)d_in[25];
    const float* out_b  = (const float*)d_in[26];
    float* out = (float*)d_out;

    float *px, *ptmp, *pq, *pk, *pv, *pctx, *ph;
    cudaGetSymbolAddress((void**)&px,   g_x);
    cudaGetSymbolAddress((void**)&ptmp, g_tmp);
    cudaGetSymbolAddress((void**)&pq,   g_q);
    cudaGetSymbolAddress((void**)&pk,   g_k);
    cudaGetSymbolAddress((void**)&pv,   g_v);
    cudaGetSymbolAddress((void**)&pctx, g_ctx);
    cudaGetSymbolAddress((void**)&ph,   g_h);

    embed_kernel<<<N_, 128>>>(src, emb);

    for (int l = 0; l < L_; l++) {
        gate_kernel<<<N_, 128>>>(gate_w + (size_t)l*D_*E_, gate_b + (size_t)l*E_);
        aux_kernel<<<1, 256>>>();

        dim3 gqkv(D_/64, N_/64, E_);
        size_t woff = (size_t)l*E_*D_*D_, boff = (size_t)l*E_*D_;
        gemm_kernel<<<gqkv, 256>>>(px, wq + woff, bq + boff, pq,
                                   N_, D_, D_, 0, (size_t)D_*D_, D_, (size_t)N_*D_, 0);
        gemm_kernel<<<gqkv, 256>>>(px, wk + woff, bk + boff, pk,
                                   N_, D_, D_, 0, (size_t)D_*D_, D_, (size_t)N_*D_, 0);
        gemm_kernel<<<gqkv, 256>>>(px, wv + woff, bv + boff, pv,
                                   N_, D_, D_, 0, (size_t)D_*D_, D_, (size_t)N_*D_, 0);

        attn_kernel<<<dim3(4, B_*E_*H_), 128>>>();

        // expert output eo = ctx @ wo + bo  (written into g_q, which is free now)
        gemm_kernel<<<gqkv, 256>>>(pctx, wo + woff, bo + boff, pq,
                                   N_, D_, D_, (size_t)N_*D_, (size_t)D_*D_, D_, (size_t)N_*D_, 0);

        combine_kernel<<<(N_*D_/4)/256, 256>>>();

        ln_kernel<<<N_, 128>>>(px, ptmp, ln1_g + (size_t)l*D_, ln1_b + (size_t)l*D_, px);
        ln_kernel<<<N_, 128>>>(px, (const float*)nullptr, ln2_g + (size_t)l*D_, ln2_b + (size_t)l*D_, px);

        gemm_kernel<<<dim3(FF_/64, N_/64), 256>>>(px, w1 + (size_t)l*D_*FF_, b1 + (size_t)l*FF_, ph,
                                                  N_, D_, FF_, 0, 0, 0, 0, 1);
        gemm_kernel<<<dim3(D_/64, N_/64), 256>>>(ph, w2 + (size_t)l*FF_*D_, b2 + (size_t)l*D_, ptmp,
                                                 N_, FF_, D_, 0, 0, 0, 0, 0);

        ln_kernel<<<N_, 128>>>(px, ptmp, ln3_g + (size_t)l*D_, ln3_b + (size_t)l*D_, px);
    }

    ln_kernel<<<N_, 128>>>(px, (const float*)nullptr, lnf_g, lnf_b, px);

    gemm_kernel<<<dim3(V_/64, N_/64), 256>>>(px, out_w, out_b, out,
                                             N_, D_, V_, 0, 0, 0, 0, 0);
    lsm_kernel<<<N_, 256>>>(out);

    if (out_size > N_*V_) {
        write_aux_kernel<<<1, 1>>>(out);
    }
}

// round 3
// speedup vs baseline: 1.0652x; 1.0652x over previous
#include <cuda_runtime.h>
#include <math.h>

#define S_ 512
#define B_ 8
#define D_ 512
#define H_ 8
#define HD_ 64
#define E_ 4
#define L_ 6
#define FF_ 2048
#define V_ 32000
#define N_ 4096          // S_*B_
#define EPS_ 1e-5f
#define NEGINF_ (-3.402823466e38f)

// ---------------- scratch (static device globals; no allocation) ----------------
__device__ float g_x[N_*D_];          // activations [N, D], n = s*B + b
__device__ float g_tmp[N_*D_];        // residual branch
__device__ float g_q[E_*N_*D_];       // Q per expert (later reused as expert-output eo)
__device__ float g_k[E_*N_*D_];
__device__ float g_v[E_*N_*D_];
__device__ float g_ctx[E_*N_*D_];
__device__ float g_h[N_*FF_];         // FFN hidden
__device__ float g_gate[N_*E_];       // softmaxed gate
__device__ float g_aux;               // aux loss accumulator

// ---------------- embed + positional encoding (+ zero aux) ----------------
__global__ void embed_kernel(const int* __restrict__ src, const float* __restrict__ emb) {
    int n = blockIdx.x;
    int s = n / B_;
    if (n == 0 && threadIdx.x == 0) g_aux = 0.f;
    int tok = src[n];
    const float scale = 22.62741699796952f;  // sqrt(512)
    for (int d = threadIdx.x; d < D_; d += blockDim.x) {
        int j = d >> 1;
        float div = expf((float)(2*j) * (-9.210340371976184f / (float)D_));
        float ang = (float)s * div;
        float pe = (d & 1) ? cosf(ang) : sinf(ang);
        g_x[(size_t)n*D_ + d] = emb[(size_t)tok*D_ + d] * scale + pe;
    }
}

// ---------------- gate: softmax(x @ gate_w + gate_b) over E=4 ----------------
__global__ void gate_kernel(const float* __restrict__ gw, const float* __restrict__ gb) {
    int n = blockIdx.x;
    int t = threadIdx.x;           // 128 threads
    float p0=0.f, p1=0.f, p2=0.f, p3=0.f;
    for (int d = t; d < D_; d += 128) {
        float xv = g_x[(size_t)n*D_ + d];
        const float* w = gw + (size_t)d*E_;
        p0 = fmaf(xv, w[0], p0);
        p1 = fmaf(xv, w[1], p1);
        p2 = fmaf(xv, w[2], p2);
        p3 = fmaf(xv, w[3], p3);
    }
    __shared__ float red[4][128];
    red[0][t]=p0; red[1][t]=p1; red[2][t]=p2; red[3][t]=p3;
    __syncthreads();
    for (int off = 64; off > 0; off >>= 1) {
        if (t < off) {
            red[0][t]+=red[0][t+off]; red[1][t]+=red[1][t+off];
            red[2][t]+=red[2][t+off]; red[3][t]+=red[3][t+off];
        }
        __syncthreads();
    }
    if (t == 0) {
        float l0=red[0][0]+gb[0], l1=red[1][0]+gb[1], l2=red[2][0]+gb[2], l3=red[3][0]+gb[3];
        float mx = fmaxf(fmaxf(l0,l1), fmaxf(l2,l3));
        float e0=expf(l0-mx), e1=expf(l1-mx), e2=expf(l2-mx), e3=expf(l3-mx);
        float inv = 1.f / (e0+e1+e2+e3);
        g_gate[n*4+0]=e0*inv; g_gate[n*4+1]=e1*inv; g_gate[n*4+2]=e2*inv; g_gate[n*4+3]=e3*inv;
    }
}

// ---------------- aux loss: importance over tokens, CV^2 accumulate ----------------
__global__ void aux_kernel() {
    __shared__ float red[4][256];
    int t = threadIdx.x;           // 256 threads
    float p[4] = {0.f,0.f,0.f,0.f};
    for (int n = t; n < N_; n += 256) {
        p[0]+=g_gate[n*4+0]; p[1]+=g_gate[n*4+1];
        p[2]+=g_gate[n*4+2]; p[3]+=g_gate[n*4+3];
    }
    red[0][t]=p[0]; red[1][t]=p[1]; red[2][t]=p[2]; red[3][t]=p[3];
    __syncthreads();
    for (int off = 128; off > 0; off >>= 1) {
        if (t < off) {
            red[0][t]+=red[0][t+off]; red[1][t]+=red[1][t+off];
            red[2][t]+=red[2][t+off]; red[3][t]+=red[3][t+off];
        }
        __syncthreads();
    }
    if (t == 0) {
        float i0=red[0][0], i1=red[1][0], i2=red[2][0], i3=red[3][0];
        float mean = (i0+i1+i2+i3)*0.25f;
        float d0=i0-mean, d1=i1-mean, d2=i2-mean, d3=i3-mean;
        float var = (d0*d0+d1*d1+d2*d2+d3*d3)*0.25f;
        g_aux += var / (mean*mean + 1e-10f);
    }
}

// ---------------- SGEMM: 128x128 tile, kc=8, 8x8 microtile, double-buffered -------
// C = A(NxK) @ W(KxM) + bias, optional relu; blockIdx.z batches via strides.
// Requires N%128==0, M%128==0, K%8==0 (all shapes here satisfy this).
__global__ __launch_bounds__(256) void gemm_kernel(
    const float* __restrict__ A, const float* __restrict__ W,
    const float* __restrict__ bias, float* __restrict__ C,
    int N, int K, int M,
    size_t az, size_t wz, size_t bz, size_t cz, int relu)
{
    A    += (size_t)blockIdx.z * az;
    W    += (size_t)blockIdx.z * wz;
    bias += (size_t)blockIdx.z * bz;
    C    += (size_t)blockIdx.z * cz;

    __shared__ float As[2][8][132];   // [buf][k][n], padded pitch
    __shared__ float Ws[2][8][128];   // [buf][k][m]

    const int t  = threadIdx.x;
    const int tx = t & 15, ty = t >> 4;           // 16x16 thread grid
    const int n0 = blockIdx.y * 128, m0 = blockIdx.x * 128;
    const int arow = t >> 1,  ak = (t & 1) * 4;   // A tile loader
    const int wk   = t >> 5,  wm = (t & 31) * 4;  // W tile loader

    const float* Ap = A + (size_t)(n0 + arow) * K + ak;
    const float* Wp = W + (size_t)wk * M + m0 + wm;
    const size_t w_step = (size_t)8 * M;

    float acc[8][8];
    #pragma unroll
    for (int i = 0; i < 8; i++)
        #pragma unroll
        for (int j = 0; j < 8; j++) acc[i][j] = 0.f;

    // prologue: chunk 0 -> buffer 0
    {
        float4 av = *(const float4*)Ap;
        float4 wv = *(const float4*)Wp;
        As[0][ak+0][arow]=av.x; As[0][ak+1][arow]=av.y;
        As[0][ak+2][arow]=av.z; As[0][ak+3][arow]=av.w;
        *(float4*)&Ws[0][wk][wm] = wv;
    }
    __syncthreads();

    const int nk = K >> 3;
    for (int kc = 0; kc < nk; kc++) {
        const int buf = kc & 1;
        float4 av, wv;
        const bool has = (kc + 1) < nk;
        if (has) {
            av = *(const float4*)(Ap + (kc + 1) * 8);
            wv = *(const float4*)(Wp + (size_t)(kc + 1) * w_step);
        }
        #pragma unroll
        for (int kk = 0; kk < 8; kk++) {
            float4 a0 = *(const float4*)&As[buf][kk][ty*8];
            float4 a1 = *(const float4*)&As[buf][kk][ty*8+4];
            float4 w0 = *(const float4*)&Ws[buf][kk][tx*8];
            float4 w1 = *(const float4*)&Ws[buf][kk][tx*8+4];
            float a[8] = {a0.x,a0.y,a0.z,a0.w,a1.x,a1.y,a1.z,a1.w};
            float w[8] = {w0.x,w0.y,w0.z,w0.w,w1.x,w1.y,w1.z,w1.w};
            #pragma unroll
            for (int i = 0; i < 8; i++)
                #pragma unroll
                for (int j = 0; j < 8; j++)
                    acc[i][j] = fmaf(a[i], w[j], acc[i][j]);
        }
        if (has) {
            const int nb = buf ^ 1;
            As[nb][ak+0][arow]=av.x; As[nb][ak+1][arow]=av.y;
            As[nb][ak+2][arow]=av.z; As[nb][ak+3][arow]=av.w;
            *(float4*)&Ws[nb][wk][wm] = wv;
        }
        __syncthreads();
    }

    const int col = m0 + tx*8;
    float4 b0 = *(const float4*)(bias + col);
    float4 b1 = *(const float4*)(bias + col + 4);
    #pragma unroll
    for (int i = 0; i < 8; i++) {
        const int row = n0 + ty*8 + i;
        float4 o0, o1;
        o0.x=acc[i][0]+b0.x; o0.y=acc[i][1]+b0.y; o0.z=acc[i][2]+b0.z; o0.w=acc[i][3]+b0.w;
        o1.x=acc[i][4]+b1.x; o1.y=acc[i][5]+b1.y; o1.z=acc[i][6]+b1.z; o1.w=acc[i][7]+b1.w;
        if (relu) {
            o0.x=fmaxf(o0.x,0.f); o0.y=fmaxf(o0.y,0.f); o0.z=fmaxf(o0.z,0.f); o0.w=fmaxf(o0.w,0.f);
            o1.x=fmaxf(o1.x,0.f); o1.y=fmaxf(o1.y,0.f); o1.z=fmaxf(o1.z,0.f); o1.w=fmaxf(o1.w,0.f);
        }
        *(float4*)(C + (size_t)row*M + col)     = o0;
        *(float4*)(C + (size_t)row*M + col + 4) = o1;
    }
}

// ---------------- causal attention per (b,e,h): chunked online softmax ------------
// grid: (4 q-chunks of 128, B*E*H=256). 128 threads; thread = one query row.
// Scores computed 16 keys at a time into registers; one rescale per 16-key chunk.
__global__ __launch_bounds__(128) void attn_kernel() {
    int qc  = blockIdx.x;
    int beh = blockIdx.y;
    int h = beh & 7;
    int e = (beh >> 3) & 3;
    int b = beh >> 5;
    int t = threadIdx.x;
    int s = qc*128 + t;

    __shared__ float4 Ks[64][16];
    __shared__ float4 Vs[64][16];

    size_t base = (size_t)e*N_*D_ + (size_t)h*HD_;
    const float* qp = g_q + base + (size_t)(s*B_+b)*D_;

    float4 q4[16];
    #pragma unroll
    for (int i=0;i<16;i++) q4[i] = *(const float4*)(qp + i*4);

    float4 a4[16];
    #pragma unroll
    for (int i=0;i<16;i++) a4[i] = make_float4(0.f,0.f,0.f,0.f);
    float m = NEGINF_, lsum = 0.f;

    int nkc = 2*qc + 2;   // key chunks of 64 needed to cover s <= qc*128+127
    for (int kc = 0; kc < nkc; kc++) {
        int j0 = kc * 64;
        __syncthreads();
        #pragma unroll
        for (int i=0;i<8;i++) {
            int idx = t + i*128;
            int j = idx >> 4, cc = idx & 15;
            size_t off = base + (size_t)((j0+j)*B_ + b)*D_ + cc*4;
            Ks[j][cc] = *(const float4*)(g_k + off);
            Vs[j][cc] = *(const float4*)(g_v + off);
        }
        __syncthreads();
        for (int sub = 0; sub < 4; sub++) {
            int j0s = j0 + sub*16;
            if (j0s > s) break;
            float sc[16];
            #pragma unroll
            for (int jj = 0; jj < 16; jj++) {
                int j = sub*16 + jj;
                float s0=0.f,s1=0.f,s2=0.f,s3=0.f;
                #pragma unroll
                for (int i=0;i<16;i++) {
                    float4 kk = Ks[j][i];
                    s0 = fmaf(q4[i].x, kk.x, s0);
                    s1 = fmaf(q4[i].y, kk.y, s1);
                    s2 = fmaf(q4[i].z, kk.z, s2);
                    s3 = fmaf(q4[i].w, kk.w, s3);
                }
                float v = ((s0+s1)+(s2+s3)) * 0.125f;   // / sqrt(64)
                sc[jj] = (j0s + jj <= s) ? v : NEGINF_;
            }
            float cm = sc[0];
            #pragma unroll
            for (int jj = 1; jj < 16; jj++) cm = fmaxf(cm, sc[jj]);
            float newm = fmaxf(m, cm);
            float alpha = __expf(m - newm);   // m==-inf first chunk -> alpha=0, acc is 0
            lsum *= alpha;
            #pragma unroll
            for (int i=0;i<16;i++) {
                a4[i].x*=alpha; a4[i].y*=alpha; a4[i].z*=alpha; a4[i].w*=alpha;
            }
            m = newm;
            #pragma unroll
            for (int jj = 0; jj < 16; jj++) {
                float p = __expf(sc[jj] - m);
                lsum += p;
                int j = sub*16 + jj;
                #pragma unroll
                for (int i=0;i<16;i++) {
                    float4 vv = Vs[j][i];
                    a4[i].x = fmaf(p, vv.x, a4[i].x);
                    a4[i].y = fmaf(p, vv.y, a4[i].y);
                    a4[i].z = fmaf(p, vv.z, a4[i].z);
                    a4[i].w = fmaf(p, vv.w, a4[i].w);
                }
            }
        }
    }
    float inv = 1.f / lsum;
    float* op = g_ctx + base + (size_t)(s*B_+b)*D_;
    #pragma unroll
    for (int i=0;i<16;i++) {
        float4 o = make_float4(a4[i].x*inv, a4[i].y*inv, a4[i].z*inv, a4[i].w*inv);
        *(float4*)(op + i*4) = o;
    }
}

// ---------------- gate-weighted expert combine: tmp = sum_e gate[n,e]*eo[e][n] ------
__global__ void combine_kernel() {
    int idx = blockIdx.x*256 + threadIdx.x;   // float4 index over N_*D_/4
    int n = idx >> 7;                         // D_/4 = 128
    const float4* eo = (const float4*)g_q;    // eo lives in g_q
    const int z = N_*D_/4;
    float g0=g_gate[n*4+0], g1=g_gate[n*4+1], g2=g_gate[n*4+2], g3=g_gate[n*4+3];
    float4 v0=eo[idx], v1=eo[z+idx], v2=eo[2*z+idx], v3=eo[3*z+idx];
    float4 r;
    r.x = g0*v0.x + g1*v1.x + g2*v2.x + g3*v3.x;
    r.y = g0*v0.y + g1*v1.y + g2*v2.y + g3*v3.y;
    r.z = g0*v0.z + g1*v1.z + g2*v2.z + g3*v3.z;
    r.w = g0*v0.w + g1*v1.w + g2*v2.w + g3*v3.w;
    ((float4*)g_tmp)[idx] = r;
}

// ---------------- LayerNorm (optional residual add), 1 block per token ----------
__device__ __forceinline__ float blocksum128(float v) {
    __shared__ float sh[4];
    #pragma unroll
    for (int o=16;o>0;o>>=1) v += __shfl_down_sync(0xffffffffu, v, o);
    __syncthreads();
    if ((threadIdx.x & 31) == 0) sh[threadIdx.x >> 5] = v;
    __syncthreads();
    return sh[0]+sh[1]+sh[2]+sh[3];
}

__global__ void ln_kernel(const float* __restrict__ xin, const float* __restrict__ res,
                          const float* __restrict__ g, const float* __restrict__ bb,
                          float* __restrict__ out) {
    int n = blockIdx.x, t = threadIdx.x;   // 128 threads, D/4 float4s
    float4 v = ((const float4*)(xin + (size_t)n*D_))[t];
    if (res) {
        float4 r = ((const float4*)(res + (size_t)n*D_))[t];
        v.x+=r.x; v.y+=r.y; v.z+=r.z; v.w+=r.w;
    }
    float mean = blocksum128(v.x+v.y+v.z+v.w) * (1.f/D_);
    float d0=v.x-mean, d1=v.y-mean, d2=v.z-mean, d3=v.w-mean;
    float var = blocksum128(d0*d0+d1*d1+d2*d2+d3*d3) * (1.f/D_);
    float rstd = rsqrtf(var + EPS_);
    float4 gg = ((const float4*)g)[t];
    float4 bv = ((const float4*)bb)[t];
    float4 o;
    o.x = d0*rstd*gg.x + bv.x;
    o.y = d1*rstd*gg.y + bv.y;
    o.z = d2*rstd*gg.z + bv.z;
    o.w = d3*rstd*gg.w + bv.w;
    ((float4*)(out + (size_t)n*D_))[t] = o;
}

// ---------------- in-place log_softmax over V per row ----------------
__global__ void lsm_kernel(float* __restrict__ out) {
    __shared__ float sh[8];
    int n = blockIdx.x, t = threadIdx.x;   // 256 threads
    float* row = out + (size_t)n*V_;
    float mx = NEGINF_;
    for (int v=t; v<V_; v+=256) mx = fmaxf(mx, row[v]);
    #pragma unroll
    for (int o=16;o>0;o>>=1) mx = fmaxf(mx, __shfl_xor_sync(0xffffffffu, mx, o));
    if ((t&31)==0) sh[t>>5]=mx;
    __syncthreads();
    mx = fmaxf(fmaxf(fmaxf(sh[0],sh[1]),fmaxf(sh[2],sh[3])),
               fmaxf(fmaxf(sh[4],sh[5]),fmaxf(sh[6],sh[7])));
    float sum = 0.f;
    for (int v=t; v<V_; v+=256) sum += expf(row[v]-mx);
    #pragma unroll
    for (int o=16;o>0;o>>=1) sum += __shfl_xor_sync(0xffffffffu, sum, o);
    __syncthreads();
    if ((t&31)==0) sh[t>>5]=sum;
    __syncthreads();
    sum = ((sh[0]+sh[1])+(sh[2]+sh[3])) + ((sh[4]+sh[5])+(sh[6]+sh[7]));
    float lse = mx + logf(sum);
    for (int v=t; v<V_; v+=256) row[v] -= lse;
}

__global__ void write_aux_kernel(float* __restrict__ out) {
    out[(size_t)N_*V_] = g_aux;
}

// ---------------- host orchestration ----------------
extern "C" void kernel_launch(void* const* d_in, const int* in_sizes, int n_in,
                              void* d_out, int out_size) {
    (void)in_sizes; (void)n_in;
    const int*   src    = (const int*)  d_in[1];
    const float* emb    = (const float*)d_in[2];
    const float* gate_w = (const float*)d_in[3];
    const float* gate_b = (const float*)d_in[4];
    const float* wq     = (const float*)d_in[5];
    const float* wk     = (const float*)d_in[6];
    const float* wv     = (const float*)d_in[7];
    const float* wo     = (const float*)d_in[8];
    const float* bq     = (const float*)d_in[9];
    const float* bk     = (const float*)d_in[10];
    const float* bv     = (const float*)d_in[11];
    const float* bo     = (const float*)d_in[12];
    const float* w1     = (const float*)d_in[13];
    const float* b1     = (const float*)d_in[14];
    const float* w2     = (const float*)d_in[15];
    const float* b2     = (const float*)d_in[16];
    const float* ln1_g  = (const float*)d_in[17];
    const float* ln1_b  = (const float*)d_in[18];
    const float* ln2_g  = (const float*)d_in[19];
    const float* ln2_b  = (const float*)d_in[20];
    const float* ln3_g  = (const float*)d_in[21];
    const float* ln3_b  = (const float*)d_in[22];
    const float* lnf_g  = (const float*)d_in[23];
    const float* lnf_b  = (const float*)d_in[24];
    const float* out_w  = (const float*)d_in[25];
    const float* out_b  = (const float*)d_in[26];
    float* out = (float*)d_out;

    float *px, *ptmp, *pq, *pk, *pv, *pctx, *ph;
    cudaGetSymbolAddress((void**)&px,   g_x);
    cudaGetSymbolAddress((void**)&ptmp, g_tmp);
    cudaGetSymbolAddress((void**)&pq,   g_q);
    cudaGetSymbolAddress((void**)&pk,   g_k);
    cudaGetSymbolAddress((void**)&pv,   g_v);
    cudaGetSymbolAddress((void**)&pctx, g_ctx);
    cudaGetSymbolAddress((void**)&ph,   g_h);

    embed_kernel<<<N_, 128>>>(src, emb);

    for (int l = 0; l < L_; l++) {
        gate_kernel<<<N_, 128>>>(gate_w + (size_t)l*D_*E_, gate_b + (size_t)l*E_);
        aux_kernel<<<1, 256>>>();

        dim3 gqkv(D_/128, N_/128, E_);
        size_t woff = (size_t)l*E_*D_*D_, boff = (size_t)l*E_*D_;
        gemm_kernel<<<gqkv, 256>>>(px, wq + woff, bq + boff, pq,
                                   N_, D_, D_, 0, (size_t)D_*D_, D_, (size_t)N_*D_, 0);
        gemm_kernel<<<gqkv, 256>>>(px, wk + woff, bk + boff, pk,
                                   N_, D_, D_, 0, (size_t)D_*D_, D_, (size_t)N_*D_, 0);
        gemm_kernel<<<gqkv, 256>>>(px, wv + woff, bv + boff, pv,
                                   N_, D_, D_, 0, (size_t)D_*D_, D_, (size_t)N_*D_, 0);

        attn_kernel<<<dim3(4, B_*E_*H_), 128>>>();

        // expert output eo = ctx @ wo + bo  (written into g_q, which is free now)
        gemm_kernel<<<gqkv, 256>>>(pctx, wo + woff, bo + boff, pq,
                                   N_, D_, D_, (size_t)N_*D_, (size_t)D_*D_, D_, (size_t)N_*D_, 0);

        combine_kernel<<<(N_*D_/4)/256, 256>>>();

        ln_kernel<<<N_, 128>>>(px, ptmp, ln1_g + (size_t)l*D_, ln1_b + (size_t)l*D_, px);
        ln_kernel<<<N_, 128>>>(px, (const float*)nullptr, ln2_g + (size_t)l*D_, ln2_b + (size_t)l*D_, px);

        gemm_kernel<<<dim3(FF_/128, N_/128), 256>>>(px, w1 + (size_t)l*D_*FF_, b1 + (size_t)l*FF_, ph,
                                                    N_, D_, FF_, 0, 0, 0, 0, 1);
        gemm_kernel<<<dim3(D_/128, N_/128), 256>>>(ph, w2 + (size_t)l*FF_*D_, b2 + (size_t)l*D_, ptmp,
                                                   N_, FF_, D_, 0, 0, 0, 0, 0);

        ln_kernel<<<N_, 128>>>(px, ptmp, ln3_g + (size_t)l*D_, ln3_b + (size_t)l*D_, px);
    }

    ln_kernel<<<N_, 128>>>(px, (const float*)nullptr, lnf_g, lnf_b, px);

    gemm_kernel<<<dim3(V_/128, N_/128), 256>>>(px, out_w, out_b, out,
                                               N_, D_, V_, 0, 0, 0, 0, 0);
    lsm_kernel<<<N_, 256>>>(out);

    if (out_size > N_*V_) {
        write_aux_kernel<<<1, 1>>>(out);
    }
}

// round 6
// speedup vs baseline: 1.8284x; 1.7165x over previous
#include <cuda_runtime.h>
#include <cuda_bf16.h>
#include <math.h>

#define S_ 512
#define B_ 8
#define D_ 512
#define H_ 8
#define HD_ 64
#define E_ 4
#define L_ 6
#define FF_ 2048
#define V_ 32000
#define N_ 4096
#define EPS_ 1e-5f
#define NEGINF_ (-3.402823466e38f)

// ---------------- scratch (static device globals; no allocation) ----------------
__device__ float g_x[N_*D_];
__device__ float g_tmp[N_*D_];
__device__ float g_q[E_*N_*D_];
__device__ float g_k[E_*N_*D_];
__device__ float g_v[E_*N_*D_];
__device__ float g_ctx[E_*N_*D_];
__device__ float g_h[N_*FF_];
__device__ float g_gate[N_*E_];
__device__ float g_aux;

// converted weights: [M][K] bf16, hi/lo split
__device__ __nv_bfloat16 g_wq_h[L_*E_*D_*D_], g_wq_l[L_*E_*D_*D_];
__device__ __nv_bfloat16 g_wk_h[L_*E_*D_*D_], g_wk_l[L_*E_*D_*D_];
__device__ __nv_bfloat16 g_wv_h[L_*E_*D_*D_], g_wv_l[L_*E_*D_*D_];
__device__ __nv_bfloat16 g_wo_h[L_*E_*D_*D_], g_wo_l[L_*E_*D_*D_];
__device__ __nv_bfloat16 g_w1_h[L_*D_*FF_],   g_w1_l[L_*D_*FF_];
__device__ __nv_bfloat16 g_w2_h[L_*FF_*D_],   g_w2_l[L_*FF_*D_];
__device__ __nv_bfloat16 g_ow_h[(size_t)D_*V_], g_ow_l[(size_t)D_*V_];

// ---------------- mma helpers ----------------
__device__ __forceinline__ void ldsm4(unsigned* r, unsigned addr)
{
    asm volatile(
        "ldmatrix.sync.aligned.m8n8.x4.shared.b16 {%0,%1,%2,%3}, [%4];"
        : "=r"(r[0]), "=r"(r[1]), "=r"(r[2]), "=r"(r[3])
        : "r"(addr));
}

__device__ __forceinline__ void mma16816(float* d, const unsigned* a, unsigned b0, unsigned b1)
{
    asm volatile(
        "mma.sync.aligned.m16n8k16.row.col.f32.bf16.bf16.f32 "
        "{%0,%1,%2,%3},{%4,%5,%6,%7},{%8,%9},{%0,%1,%2,%3};"
        : "+f"(d[0]), "+f"(d[1]), "+f"(d[2]), "+f"(d[3])
        : "r"(a[0]), "r"(a[1]), "r"(a[2]), "r"(a[3]), "r"(b0), "r"(b1));
}

// ---------------- weight convert: W[K][M] fp32 -> Hi/Lo[M][K] bf16 ----------------
__global__ __launch_bounds__(256) void convert_w(
    const float* __restrict__ W, __nv_bfloat16* __restrict__ Hi,
    __nv_bfloat16* __restrict__ Lo, int K, int M, size_t inz, size_t outz)
{
    W  += (size_t)blockIdx.z * inz;
    Hi += (size_t)blockIdx.z * outz;
    Lo += (size_t)blockIdx.z * outz;
    __shared__ float tile[32][33];
    int m0 = blockIdx.x * 32, k0 = blockIdx.y * 32;
    int tx = threadIdx.x & 31, ty = threadIdx.x >> 5;
    #pragma unroll
    for (int i = 0; i < 32; i += 8)
        tile[ty + i][tx] = W[(size_t)(k0 + ty + i) * M + m0 + tx];
    __syncthreads();
    #pragma unroll
    for (int i = 0; i < 32; i += 8) {
        float v = tile[tx][ty + i];
        __nv_bfloat16 h = __float2bfloat16(v);
        float r = v - __bfloat162float(h);
        size_t o = (size_t)(m0 + ty + i) * K + k0 + tx;
        Hi[o] = h;
        Lo[o] = __float2bfloat16(r);
    }
}

// ---------------- embed + positional encoding (+ zero aux) ----------------
__global__ void embed_kernel(const int* __restrict__ src, const float* __restrict__ emb)
{
    int n = blockIdx.x;
    int s = n / B_;
    if (n == 0 && threadIdx.x == 0) g_aux = 0.f;
    int tok = src[n];
    const float scale = 22.62741699796952f;
    for (int d = threadIdx.x; d < D_; d += blockDim.x) {
        int j = d >> 1;
        float div = expf((float)(2*j) * (-9.210340371976184f / (float)D_));
        float ang = (float)s * div;
        float pe = (d & 1) ? cosf(ang) : sinf(ang);
        g_x[(size_t)n*D_ + d] = emb[(size_t)tok*D_ + d] * scale + pe;
    }
}

// ---------------- gate: softmax(x @ gate_w + gate_b) over E=4 ----------------
__global__ void gate_kernel(const float* __restrict__ gw, const float* __restrict__ gb)
{
    int n = blockIdx.x;
    int t = threadIdx.x;
    float p0=0.f, p1=0.f, p2=0.f, p3=0.f;
    for (int d = t; d < D_; d += 128) {
        float xv = g_x[(size_t)n*D_ + d];
        const float* w = gw + (size_t)d*E_;
        p0 = fmaf(xv, w[0], p0);
        p1 = fmaf(xv, w[1], p1);
        p2 = fmaf(xv, w[2], p2);
        p3 = fmaf(xv, w[3], p3);
    }
    __shared__ float red[4][128];
    red[0][t]=p0; red[1][t]=p1; red[2][t]=p2; red[3][t]=p3;
    __syncthreads();
    for (int off = 64; off > 0; off >>= 1) {
        if (t < off) {
            red[0][t]+=red[0][t+off]; red[1][t]+=red[1][t+off];
            red[2][t]+=red[2][t+off]; red[3][t]+=red[3][t+off];
        }
        __syncthreads();
    }
    if (t == 0) {
        float l0=red[0][0]+gb[0], l1=red[1][0]+gb[1], l2=red[2][0]+gb[2], l3=red[3][0]+gb[3];
        float mx = fmaxf(fmaxf(l0,l1), fmaxf(l2,l3));
        float e0=expf(l0-mx), e1=expf(l1-mx), e2=expf(l2-mx), e3=expf(l3-mx);
        float inv = 1.f / (e0+e1+e2+e3);
        g_gate[n*4+0]=e0*inv; g_gate[n*4+1]=e1*inv; g_gate[n*4+2]=e2*inv; g_gate[n*4+3]=e3*inv;
    }
}

// ---------------- aux loss ----------------
__global__ void aux_kernel()
{
    __shared__ float red[4][256];
    int t = threadIdx.x;
    float p0=0.f, p1=0.f, p2=0.f, p3=0.f;
    for (int n = t; n < N_; n += 256) {
        p0+=g_gate[n*4+0]; p1+=g_gate[n*4+1];
        p2+=g_gate[n*4+2]; p3+=g_gate[n*4+3];
    }
    red[0][t]=p0; red[1][t]=p1; red[2][t]=p2; red[3][t]=p3;
    __syncthreads();
    for (int off = 128; off > 0; off >>= 1) {
        if (t < off) {
            red[0][t]+=red[0][t+off]; red[1][t]+=red[1][t+off];
            red[2][t]+=red[2][t+off]; red[3][t]+=red[3][t+off];
        }
        __syncthreads();
    }
    if (t == 0) {
        float i0=red[0][0], i1=red[1][0], i2=red[2][0], i3=red[3][0];
        float mean = (i0+i1+i2+i3)*0.25f;
        float d0=i0-mean, d1=i1-mean, d2=i2-mean, d3=i3-mean;
        float var = (d0*d0+d1*d1+d2*d2+d3*d3)*0.25f;
        g_aux += var / (mean*mean + 1e-10f);
    }
}

// ---------------- tensor-core GEMM: C = A(fp32 NxK) @ W(bf16-split [M][K]) + bias ---
// Tile: 128 rows x 64 cols, K-chunk 32, 256 threads (8 warps, 4x2).
// Split-bf16: C += Ah*Wh + Ah*Wl + Al*Wh via mma.sync.m16n8k16.
#define APITCH 40

__global__ __launch_bounds__(256) void gemm_mma(
    const float* __restrict__ A,
    const __nv_bfloat16* __restrict__ Wh, const __nv_bfloat16* __restrict__ Wl,
    const float* __restrict__ bias, float* __restrict__ C,
    int N, int K, int M,
    size_t az, size_t wz, size_t bz, size_t cz, int relu)
{
    A    += (size_t)blockIdx.z * az;
    Wh   += (size_t)blockIdx.z * wz;
    Wl   += (size_t)blockIdx.z * wz;
    bias += (size_t)blockIdx.z * bz;
    C    += (size_t)blockIdx.z * cz;

    __shared__ __nv_bfloat16 sAh[128*APITCH];
    __shared__ __nv_bfloat16 sAl[128*APITCH];
    __shared__ __nv_bfloat16 sBh[64*APITCH];
    __shared__ __nv_bfloat16 sBl[64*APITCH];

    const int t = threadIdx.x;
    const int lane = t & 31;
    const int wid = t >> 5;
    const int n0 = blockIdx.y * 128;
    const int m0 = blockIdx.x * 64;
    const int wm = (wid >> 1) * 32;
    const int wn = (wid & 1) * 32;

    const int lrow = lane & 15;
    const int lk = (lane >> 4) * 8;
    const unsigned aBaseH = (unsigned)__cvta_generic_to_shared(sAh) + (unsigned)(((wm + lrow)*APITCH + lk)*2);
    const unsigned aBaseL = (unsigned)__cvta_generic_to_shared(sAl) + (unsigned)(((wm + lrow)*APITCH + lk)*2);
    const unsigned bBaseH = (unsigned)__cvta_generic_to_shared(sBh) + (unsigned)(((wn + lrow)*APITCH + lk)*2);
    const unsigned bBaseL = (unsigned)__cvta_generic_to_shared(sBl) + (unsigned)(((wn + lrow)*APITCH + lk)*2);

    float acc[2][4][4];
    #pragma unroll
    for (int i = 0; i < 2; i++) {
        #pragma unroll
        for (int j = 0; j < 4; j++) {
            #pragma unroll
            for (int c = 0; c < 4; c++) {
                acc[i][j][c] = 0.f;
            }
        }
    }

    const int brow = t >> 2;
    const int bkq = (t & 3) * 8;

    for (int k0 = 0; k0 < K; k0 += 32) {
        // A tile 128x32 fp32 -> hi/lo bf16
        #pragma unroll
        for (int i = 0; i < 4; i++) {
            int idx = t + i*256;
            int row = idx >> 3;
            int kq = (idx & 7) * 4;
            float4 v = *(const float4*)(A + (size_t)(n0+row)*K + k0 + kq);
            __nv_bfloat16 h0 = __float2bfloat16(v.x);
            __nv_bfloat16 h1 = __float2bfloat16(v.y);
            __nv_bfloat16 h2 = __float2bfloat16(v.z);
            __nv_bfloat16 h3 = __float2bfloat16(v.w);
            __nv_bfloat16 e0 = __float2bfloat16(v.x - __bfloat162float(h0));
            __nv_bfloat16 e1 = __float2bfloat16(v.y - __bfloat162float(h1));
            __nv_bfloat16 e2 = __float2bfloat16(v.z - __bfloat162float(h2));
            __nv_bfloat16 e3 = __float2bfloat16(v.w - __bfloat162float(h3));
            __nv_bfloat162* ph = (__nv_bfloat162*)(sAh + row*APITCH + kq);
            __nv_bfloat162* pl = (__nv_bfloat162*)(sAl + row*APITCH + kq);
            ph[0] = __halves2bfloat162(h0, h1);
            ph[1] = __halves2bfloat162(h2, h3);
            pl[0] = __halves2bfloat162(e0, e1);
            pl[1] = __halves2bfloat162(e2, e3);
        }
        // B tiles 64x32 bf16 hi/lo
        {
            const __nv_bfloat16* gh = Wh + (size_t)(m0+brow)*K + k0 + bkq;
            const __nv_bfloat16* gl = Wl + (size_t)(m0+brow)*K + k0 + bkq;
            uint4 vh = *(const uint4*)gh;
            uint4 vl = *(const uint4*)gl;
            unsigned* ph = (unsigned*)(sBh + brow*APITCH + bkq);
            unsigned* pl = (unsigned*)(sBl + brow*APITCH + bkq);
            ph[0] = vh.x; ph[1] = vh.y; ph[2] = vh.z; ph[3] = vh.w;
            pl[0] = vl.x; pl[1] = vl.y; pl[2] = vl.z; pl[3] = vl.w;
        }
        __syncthreads();

        #pragma unroll
        for (int ks = 0; ks < 2; ks++) {
            unsigned ko = (unsigned)(ks * 32);
            unsigned aH[2][4];
            unsigned aL[2][4];
            unsigned bH[2][4];
            unsigned bL[2][4];
            ldsm4(aH[0], aBaseH + ko);
            ldsm4(aH[1], aBaseH + 1280u + ko);
            ldsm4(aL[0], aBaseL + ko);
            ldsm4(aL[1], aBaseL + 1280u + ko);
            ldsm4(bH[0], bBaseH + ko);
            ldsm4(bH[1], bBaseH + 1280u + ko);
            ldsm4(bL[0], bBaseL + ko);
            ldsm4(bL[1], bBaseL + 1280u + ko);
            #pragma unroll
            for (int mt = 0; mt < 2; mt++) {
                #pragma unroll
                for (int np = 0; np < 2; np++) {
                    #pragma unroll
                    for (int sub = 0; sub < 2; sub++) {
                        float* d = acc[mt][np*2 + sub];
                        mma16816(d, aH[mt], bH[np][sub], bH[np][sub+2]);
                        mma16816(d, aH[mt], bL[np][sub], bL[np][sub+2]);
                        mma16816(d, aL[mt], bH[np][sub], bH[np][sub+2]);
                    }
                }
            }
        }
        __syncthreads();
    }

    const int gr = lane >> 2;
    const int q = lane & 3;
    #pragma unroll
    for (int mt = 0; mt < 2; mt++) {
        int row = n0 + wm + mt*16 + gr;
        #pragma unroll
        for (int nt = 0; nt < 4; nt++) {
            int col = m0 + wn + nt*8 + q*2;
            float bx = bias[col];
            float by = bias[col+1];
            float c0 = acc[mt][nt][0] + bx;
            float c1 = acc[mt][nt][1] + by;
            float c2 = acc[mt][nt][2] + bx;
            float c3 = acc[mt][nt][3] + by;
            if (relu) {
                c0 = fmaxf(c0, 0.f); c1 = fmaxf(c1, 0.f);
                c2 = fmaxf(c2, 0.f); c3 = fmaxf(c3, 0.f);
            }
            *(float2*)(C + (size_t)row*M + col)     = make_float2(c0, c1);
            *(float2*)(C + (size_t)(row+8)*M + col) = make_float2(c2, c3);
        }
    }
}

// ---------------- causal attention per (b,e,h): chunked online softmax ------------
__global__ __launch_bounds__(128) void attn_kernel()
{
    int qc  = blockIdx.x;
    int beh = blockIdx.y;
    int h = beh & 7;
    int e = (beh >> 3) & 3;
    int b = beh >> 5;
    int t = threadIdx.x;
    int s = qc*128 + t;

    __shared__ float4 Ks[64][16];
    __shared__ float4 Vs[64][16];

    size_t base = (size_t)e*N_*D_ + (size_t)h*HD_;
    const float* qp = g_q + base + (size_t)(s*B_+b)*D_;

    float4 q4[16];
    #pragma unroll
    for (int i = 0; i < 16; i++) q4[i] = *(const float4*)(qp + i*4);

    float4 a4[16];
    #pragma unroll
    for (int i = 0; i < 16; i++) a4[i] = make_float4(0.f, 0.f, 0.f, 0.f);
    float m = NEGINF_, lsum = 0.f;

    int nkc = 2*qc + 2;
    for (int kc = 0; kc < nkc; kc++) {
        int j0 = kc * 64;
        __syncthreads();
        #pragma unroll
        for (int i = 0; i < 8; i++) {
            int idx = t + i*128;
            int j = idx >> 4;
            int cc = idx & 15;
            size_t off = base + (size_t)((j0+j)*B_ + b)*D_ + cc*4;
            Ks[j][cc] = *(const float4*)(g_k + off);
            Vs[j][cc] = *(const float4*)(g_v + off);
        }
        __syncthreads();
        for (int sub = 0; sub < 4; sub++) {
            int j0s = j0 + sub*16;
            if (j0s > s) break;
            float sc[16];
            #pragma unroll
            for (int jj = 0; jj < 16; jj++) {
                int j = sub*16 + jj;
                float s0=0.f, s1=0.f, s2=0.f, s3=0.f;
                #pragma unroll
                for (int i = 0; i < 16; i++) {
                    float4 kk = Ks[j][i];
                    s0 = fmaf(q4[i].x, kk.x, s0);
                    s1 = fmaf(q4[i].y, kk.y, s1);
                    s2 = fmaf(q4[i].z, kk.z, s2);
                    s3 = fmaf(q4[i].w, kk.w, s3);
                }
                float v = ((s0+s1)+(s2+s3)) * 0.125f;
                sc[jj] = (j0s + jj <= s) ? v : NEGINF_;
            }
            float cm = sc[0];
            #pragma unroll
            for (int jj = 1; jj < 16; jj++) cm = fmaxf(cm, sc[jj]);
            float newm = fmaxf(m, cm);
            float alpha = __expf(m - newm);
            lsum *= alpha;
            #pragma unroll
            for (int i = 0; i < 16; i++) {
                a4[i].x *= alpha; a4[i].y *= alpha;
                a4[i].z *= alpha; a4[i].w *= alpha;
            }
            m = newm;
            #pragma unroll
            for (int jj = 0; jj < 16; jj++) {
                float p = __expf(sc[jj] - m);
                lsum += p;
                int j = sub*16 + jj;
                #pragma unroll
                for (int i = 0; i < 16; i++) {
                    float4 vv = Vs[j][i];
                    a4[i].x = fmaf(p, vv.x, a4[i].x);
                    a4[i].y = fmaf(p, vv.y, a4[i].y);
                    a4[i].z = fmaf(p, vv.z, a4[i].z);
                    a4[i].w = fmaf(p, vv.w, a4[i].w);
                }
            }
        }
    }
    float inv = 1.f / lsum;
    float* op = g_ctx + base + (size_t)(s*B_+b)*D_;
    #pragma unroll
    for (int i = 0; i < 16; i++) {
        float4 o = make_float4(a4[i].x*inv, a4[i].y*inv, a4[i].z*inv, a4[i].w*inv);
        *(float4*)(op + i*4) = o;
    }
}

// ---------------- gate-weighted expert combine ----------------
__global__ void combine_kernel()
{
    int idx = blockIdx.x*256 + threadIdx.x;
    int n = idx >> 7;
    const float4* eo = (const float4*)g_q;
    const int z = N_*D_/4;
    float g0 = g_gate[n*4+0];
    float g1 = g_gate[n*4+1];
    float g2 = g_gate[n*4+2];
    float g3 = g_gate[n*4+3];
    float4 v0 = eo[idx];
    float4 v1 = eo[z+idx];
    float4 v2 = eo[2*z+idx];
    float4 v3 = eo[3*z+idx];
    float4 r;
    r.x = g0*v0.x + g1*v1.x + g2*v2.x + g3*v3.x;
    r.y = g0*v0.y + g1*v1.y + g2*v2.y + g3*v3.y;
    r.z = g0*v0.z + g1*v1.z + g2*v2.z + g3*v3.z;
    r.w = g0*v0.w + g1*v1.w + g2*v2.w + g3*v3.w;
    ((float4*)g_tmp)[idx] = r;
}

// ---------------- LayerNorm ----------------
__device__ __forceinline__ float blocksum128(float v)
{
    __shared__ float sh[4];
    #pragma unroll
    for (int o = 16; o > 0; o >>= 1) v += __shfl_down_sync(0xffffffffu, v, o);
    __syncthreads();
    if ((threadIdx.x & 31) == 0) sh[threadIdx.x >> 5] = v;
    __syncthreads();
    return sh[0] + sh[1] + sh[2] + sh[3];
}

__global__ void ln_kernel(const float* __restrict__ xin, const float* __restrict__ res,
                          const float* __restrict__ g, const float* __restrict__ bb,
                          float* __restrict__ out)
{
    int n = blockIdx.x;
    int t = threadIdx.x;
    float4 v = ((const float4*)(xin + (size_t)n*D_))[t];
    if (res) {
        float4 r = ((const float4*)(res + (size_t)n*D_))[t];
        v.x += r.x; v.y += r.y; v.z += r.z; v.w += r.w;
    }
    float mean = blocksum128(v.x+v.y+v.z+v.w) * (1.f/D_);
    float d0 = v.x-mean, d1 = v.y-mean, d2 = v.z-mean, d3 = v.w-mean;
    float var = blocksum128(d0*d0 + d1*d1 + d2*d2 + d3*d3) * (1.f/D_);
    float rstd = rsqrtf(var + EPS_);
    float4 gg = ((const float4*)g)[t];
    float4 bv = ((const float4*)bb)[t];
    float4 o;
    o.x = d0*rstd*gg.x + bv.x;
    o.y = d1*rstd*gg.y + bv.y;
    o.z = d2*rstd*gg.z + bv.z;
    o.w = d3*rstd*gg.w + bv.w;
    ((float4*)(out + (size_t)n*D_))[t] = o;
}

// ---------------- in-place log_softmax over V per row ----------------
__global__ void lsm_kernel(float* __restrict__ out)
{
    __shared__ float sh[8];
    int n = blockIdx.x;
    int t = threadIdx.x;
    float* row = out + (size_t)n*V_;
    float mx = NEGINF_;
    for (int v = t; v < V_; v += 256) mx = fmaxf(mx, row[v]);
    #pragma unroll
    for (int o = 16; o > 0; o >>= 1) mx = fmaxf(mx, __shfl_xor_sync(0xffffffffu, mx, o));
    if ((t & 31) == 0) sh[t >> 5] = mx;
    __syncthreads();
    mx = fmaxf(fmaxf(fmaxf(sh[0],sh[1]), fmaxf(sh[2],sh[3])),
               fmaxf(fmaxf(sh[4],sh[5]), fmaxf(sh[6],sh[7])));
    float sum = 0.f;
    for (int v = t; v < V_; v += 256) sum += expf(row[v] - mx);
    #pragma unroll
    for (int o = 16; o > 0; o >>= 1) sum += __shfl_xor_sync(0xffffffffu, sum, o);
    __syncthreads();
    if ((t & 31) == 0) sh[t >> 5] = sum;
    __syncthreads();
    sum = ((sh[0]+sh[1]) + (sh[2]+sh[3])) + ((sh[4]+sh[5]) + (sh[6]+sh[7]));
    float lse = mx + logf(sum);
    for (int v = t; v < V_; v += 256) row[v] -= lse;
}

__global__ void write_aux_kernel(float* __restrict__ out)
{
    out[(size_t)N_*V_] = g_aux;
}

// ---------------- host orchestration ----------------
extern "C" void kernel_launch(void* const* d_in, const int* in_sizes, int n_in,
                              void* d_out, int out_size)
{
    (void)in_sizes; (void)n_in;
    const int*   src    = (const int*)  d_in[1];
    const float* emb    = (const float*)d_in[2];
    const float* gate_w = (const float*)d_in[3];
    const float* gate_b = (const float*)d_in[4];
    const float* wq     = (const float*)d_in[5];
    const float* wk     = (const float*)d_in[6];
    const float* wv     = (const float*)d_in[7];
    const float* wo     = (const float*)d_in[8];
    const float* bq     = (const float*)d_in[9];
    const float* bk     = (const float*)d_in[10];
    const float* bv     = (const float*)d_in[11];
    const float* bo     = (const float*)d_in[12];
    const float* w1     = (const float*)d_in[13];
    const float* b1     = (const float*)d_in[14];
    const float* w2     = (const float*)d_in[15];
    const float* b2     = (const float*)d_in[16];
    const float* ln1_g  = (const float*)d_in[17];
    const float* ln1_b  = (const float*)d_in[18];
    const float* ln2_g  = (const float*)d_in[19];
    const float* ln2_b  = (const float*)d_in[20];
    const float* ln3_g  = (const float*)d_in[21];
    const float* ln3_b  = (const float*)d_in[22];
    const float* lnf_g  = (const float*)d_in[23];
    const float* lnf_b  = (const float*)d_in[24];
    const float* out_w  = (const float*)d_in[25];
    const float* out_b  = (const float*)d_in[26];
    float* out = (float*)d_out;

    float *px, *ptmp, *pq, *pk, *pv, *pctx, *ph;
    cudaGetSymbolAddress((void**)&px,   g_x);
    cudaGetSymbolAddress((void**)&ptmp, g_tmp);
    cudaGetSymbolAddress((void**)&pq,   g_q);
    cudaGetSymbolAddress((void**)&pk,   g_k);
    cudaGetSymbolAddress((void**)&pv,   g_v);
    cudaGetSymbolAddress((void**)&pctx, g_ctx);
    cudaGetSymbolAddress((void**)&ph,   g_h);

    __nv_bfloat16 *pwq_h, *pwq_l, *pwk_h, *pwk_l, *pwv_h, *pwv_l, *pwo_h, *pwo_l;
    __nv_bfloat16 *pw1_h, *pw1_l, *pw2_h, *pw2_l, *pow_h, *pow_l;
    cudaGetSymbolAddress((void**)&pwq_h, g_wq_h);
    cudaGetSymbolAddress((void**)&pwq_l, g_wq_l);
    cudaGetSymbolAddress((void**)&pwk_h, g_wk_h);
    cudaGetSymbolAddress((void**)&pwk_l, g_wk_l);
    cudaGetSymbolAddress((void**)&pwv_h, g_wv_h);
    cudaGetSymbolAddress((void**)&pwv_l, g_wv_l);
    cudaGetSymbolAddress((void**)&pwo_h, g_wo_h);
    cudaGetSymbolAddress((void**)&pwo_l, g_wo_l);
    cudaGetSymbolAddress((void**)&pw1_h, g_w1_h);
    cudaGetSymbolAddress((void**)&pw1_l, g_w1_l);
    cudaGetSymbolAddress((void**)&pw2_h, g_w2_h);
    cudaGetSymbolAddress((void**)&pw2_l, g_w2_l);
    cudaGetSymbolAddress((void**)&pow_h, g_ow_h);
    cudaGetSymbolAddress((void**)&pow_l, g_ow_l);

    size_t dd = (size_t)D_*D_;
    convert_w<<<dim3(D_/32, D_/32, L_*E_), 256>>>(wq, pwq_h, pwq_l, D_, D_, dd, dd);
    convert_w<<<dim3(D_/32, D_/32, L_*E_), 256>>>(wk, pwk_h, pwk_l, D_, D_, dd, dd);
    convert_w<<<dim3(D_/32, D_/32, L_*E_), 256>>>(wv, pwv_h, pwv_l, D_, D_, dd, dd);
    convert_w<<<dim3(D_/32, D_/32, L_*E_), 256>>>(wo, pwo_h, pwo_l, D_, D_, dd, dd);
    convert_w<<<dim3(FF_/32, D_/32, L_), 256>>>(w1, pw1_h, pw1_l, D_, FF_, (size_t)D_*FF_, (size_t)D_*FF_);
    convert_w<<<dim3(D_/32, FF_/32, L_), 256>>>(w2, pw2_h, pw2_l, FF_, D_, (size_t)FF_*D_, (size_t)FF_*D_);
    convert_w<<<dim3(V_/32, D_/32, 1), 256>>>(out_w, pow_h, pow_l, D_, V_, 0, 0);

    embed_kernel<<<N_, 128>>>(src, emb);

    for (int l = 0; l < L_; l++) {
        gate_kernel<<<N_, 128>>>(gate_w + (size_t)l*D_*E_, gate_b + (size_t)l*E_);
        aux_kernel<<<1, 256>>>();

        dim3 gqkv(D_/64, N_/128, E_);
        size_t woff = (size_t)l*E_*dd;
        size_t boff = (size_t)l*E_*D_;
        gemm_mma<<<gqkv, 256>>>(px, pwq_h + woff, pwq_l + woff, bq + boff, pq,
                                N_, D_, D_, 0, dd, D_, (size_t)N_*D_, 0);
        gemm_mma<<<gqkv, 256>>>(px, pwk_h + woff, pwk_l + woff, bk + boff, pk,
                                N_, D_, D_, 0, dd, D_, (size_t)N_*D_, 0);
        gemm_mma<<<gqkv, 256>>>(px, pwv_h + woff, pwv_l + woff, bv + boff, pv,
                                N_, D_, D_, 0, dd, D_, (size_t)N_*D_, 0);

        attn_kernel<<<dim3(4, B_*E_*H_), 128>>>();

        gemm_mma<<<gqkv, 256>>>(pctx, pwo_h + woff, pwo_l + woff, bo + boff, pq,
                                N_, D_, D_, (size_t)N_*D_, dd, D_, (size_t)N_*D_, 0);

        combine_kernel<<<(N_*D_/4)/256, 256>>>();

        ln_kernel<<<N_, 128>>>(px, ptmp, ln1_g + (size_t)l*D_, ln1_b + (size_t)l*D_, px);
        ln_kernel<<<N_, 128>>>(px, (const float*)0, ln2_g + (size_t)l*D_, ln2_b + (size_t)l*D_, px);

        gemm_mma<<<dim3(FF_/64, N_/128), 256>>>(px, pw1_h + (size_t)l*D_*FF_, pw1_l + (size_t)l*D_*FF_,
                                                b1 + (size_t)l*FF_, ph, N_, D_, FF_, 0, 0, 0, 0, 1);
        gemm_mma<<<dim3(D_/64, N_/128), 256>>>(ph, pw2_h + (size_t)l*FF_*D_, pw2_l + (size_t)l*FF_*D_,
                                               b2 + (size_t)l*D_, ptmp, N_, FF_, D_, 0, 0, 0, 0, 0);

        ln_kernel<<<N_, 128>>>(px, ptmp, ln3_g + (size_t)l*D_, ln3_b + (size_t)l*D_, px);
    }

    ln_kernel<<<N_, 128>>>(px, (const float*)0, lnf_g, lnf_b, px);

    gemm_mma<<<dim3(V_/64, N_/128), 256>>>(px, pow_h, pow_l, out_b, out,
                                           N_, D_, V_, 0, 0, 0, 0, 0);
    lsm_kernel<<<N_, 256>>>(out);

    if (out_size > N_*V_) {
        write_aux_kernel<<<1, 1>>>(out);
    }
}